// round 1
// baseline (speedup 1.0000x reference)
#include <cuda_runtime.h>
#include <cuda_bf16.h>

// Problem constants
#define BATCH 2
#define SEQ   2048
#define DM    1024
#define NH    16
#define DH    64
#define MTOT  (BATCH*SEQ)   // 4096 rows

// Scratch for Q, K, V projections: [B*T, DM] each, fp32. 16MB each.
__device__ float g_Q[MTOT*DM];
__device__ float g_K[MTOT*DM];
__device__ float g_V[MTOT*DM];

// ---------------------------------------------------------------------------
// QKV projection GEMM: Y[m,n] = sum_k X[m,k] * W[n,k]
// M=4096, N=1024, K=1024. 64x64 block tile, Ktile=16, 256 threads, 4x4 micro.
// blockIdx.z selects which of Wq/Wk/Wv and the matching output buffer.
// ---------------------------------------------------------------------------
__global__ __launch_bounds__(256) void qkv_gemm_kernel(
    const float* __restrict__ X,
    const float* __restrict__ Wq,
    const float* __restrict__ Wk,
    const float* __restrict__ Wv)
{
    const float* W;
    float* Y;
    if (blockIdx.z == 0)      { W = Wq; Y = g_Q; }
    else if (blockIdx.z == 1) { W = Wk; Y = g_K; }
    else                      { W = Wv; Y = g_V; }

    __shared__ float Xs[16][64];   // [k][m]
    __shared__ float Ws[16][64];   // [k][n]

    const int m0 = blockIdx.y * 64;
    const int n0 = blockIdx.x * 64;
    const int tid = threadIdx.x;
    const int tx = tid & 15;        // 0..15 -> n
    const int ty = tid >> 4;        // 0..15 -> m

    // loader coords: each thread loads one float4 per tile per matrix
    const int lr = tid >> 2;        // 0..63 row within tile
    const int lk = (tid & 3) << 2;  // 0,4,8,12 k offset

    float acc[4][4] = {};

    for (int k0 = 0; k0 < DM; k0 += 16) {
        float4 xv = *(const float4*)&X[(size_t)(m0 + lr) * DM + k0 + lk];
        float4 wv = *(const float4*)&W[(size_t)(n0 + lr) * DM + k0 + lk];
        Xs[lk + 0][lr] = xv.x; Xs[lk + 1][lr] = xv.y;
        Xs[lk + 2][lr] = xv.z; Xs[lk + 3][lr] = xv.w;
        Ws[lk + 0][lr] = wv.x; Ws[lk + 1][lr] = wv.y;
        Ws[lk + 2][lr] = wv.z; Ws[lk + 3][lr] = wv.w;
        __syncthreads();

        #pragma unroll
        for (int kk = 0; kk < 16; kk++) {
            float4 a = *(const float4*)&Xs[kk][ty << 2];
            float4 b = *(const float4*)&Ws[kk][tx << 2];
            acc[0][0] += a.x * b.x; acc[0][1] += a.x * b.y; acc[0][2] += a.x * b.z; acc[0][3] += a.x * b.w;
            acc[1][0] += a.y * b.x; acc[1][1] += a.y * b.y; acc[1][2] += a.y * b.z; acc[1][3] += a.y * b.w;
            acc[2][0] += a.z * b.x; acc[2][1] += a.z * b.y; acc[2][2] += a.z * b.z; acc[2][3] += a.z * b.w;
            acc[3][0] += a.w * b.x; acc[3][1] += a.w * b.y; acc[3][2] += a.w * b.z; acc[3][3] += a.w * b.w;
        }
        __syncthreads();
    }

    #pragma unroll
    for (int i = 0; i < 4; i++) {
        float4 v = make_float4(acc[i][0], acc[i][1], acc[i][2], acc[i][3]);
        *(float4*)&Y[(size_t)(m0 + (ty << 2) + i) * DM + n0 + (tx << 2)] = v;
    }
}

// ---------------------------------------------------------------------------
// Flash-style causal attention.
// Grid: (qtile=SEQ/64, head=NH, batch=BATCH). 256 threads.
// Q tile: 64 rows x 64 dims. K/V tiles: 32 rows x 64 dims.
// Thread layout 16x16: each thread owns S[4 rows][2 cols], O[4 rows][4 dims].
// Row stats reduced across the 16 lanes sharing ty via shfl.xor {1,2,4,8}.
// ---------------------------------------------------------------------------
__global__ __launch_bounds__(256) void attn_kernel(float* __restrict__ out)
{
    const int qt = blockIdx.x;
    const int h  = blockIdx.y;
    const int b  = blockIdx.z;

    __shared__ float Qs[64][65];
    __shared__ float Ks[32][65];
    __shared__ float Vs[32][65];
    __shared__ float Ps[64][33];

    const int tid = threadIdx.x;
    const int tx = tid & 15;
    const int ty = tid >> 4;

    const float* Qg = g_Q + (size_t)b * SEQ * DM + (size_t)h * DH;
    const float* Kg = g_K + (size_t)b * SEQ * DM + (size_t)h * DH;
    const float* Vg = g_V + (size_t)b * SEQ * DM + (size_t)h * DH;

    // Load Q tile (64 x 64)
    for (int i = tid; i < 64 * 16; i += 256) {
        int r  = i >> 4;
        int c4 = (i & 15) << 2;
        float4 v = *(const float4*)&Qg[(size_t)(qt * 64 + r) * DM + c4];
        Qs[r][c4 + 0] = v.x; Qs[r][c4 + 1] = v.y;
        Qs[r][c4 + 2] = v.z; Qs[r][c4 + 3] = v.w;
    }

    float m_i[4], l_i[4];
    float O[4][4] = {};
    #pragma unroll
    for (int i = 0; i < 4; i++) { m_i[i] = -1e30f; l_i[i] = 0.0f; }

    const float scale = 0.125f;               // 1/sqrt(64)
    const int jmax = 2 * qt + 1;              // last 32-row KV tile touching this Q tile

    for (int j = 0; j <= jmax; j++) {
        __syncthreads();   // prior iter done reading Ks/Vs/Ps
        // Load K, V tiles (32 x 64 each)
        for (int i = tid; i < 32 * 16; i += 256) {
            int r  = i >> 4;
            int c4 = (i & 15) << 2;
            float4 kv = *(const float4*)&Kg[(size_t)(j * 32 + r) * DM + c4];
            float4 vv = *(const float4*)&Vg[(size_t)(j * 32 + r) * DM + c4];
            Ks[r][c4 + 0] = kv.x; Ks[r][c4 + 1] = kv.y;
            Ks[r][c4 + 2] = kv.z; Ks[r][c4 + 3] = kv.w;
            Vs[r][c4 + 0] = vv.x; Vs[r][c4 + 1] = vv.y;
            Vs[r][c4 + 2] = vv.z; Vs[r][c4 + 3] = vv.w;
        }
        __syncthreads();

        // S[4][2] = Q tile rows (ty*4+i) x K tile rows (tx*2+jj)
        float S[4][2] = {};
        #pragma unroll
        for (int kk = 0; kk < 64; kk++) {
            float a0 = Qs[(ty << 2) + 0][kk];
            float a1 = Qs[(ty << 2) + 1][kk];
            float a2 = Qs[(ty << 2) + 2][kk];
            float a3 = Qs[(ty << 2) + 3][kk];
            float b0 = Ks[(tx << 1) + 0][kk];
            float b1 = Ks[(tx << 1) + 1][kk];
            S[0][0] += a0 * b0; S[0][1] += a0 * b1;
            S[1][0] += a1 * b0; S[1][1] += a1 * b1;
            S[2][0] += a2 * b0; S[2][1] += a2 * b1;
            S[3][0] += a3 * b0; S[3][1] += a3 * b1;
        }

        // mask + scale, online softmax
        #pragma unroll
        for (int i = 0; i < 4; i++) {
            int grow = qt * 64 + (ty << 2) + i;
            #pragma unroll
            for (int jj = 0; jj < 2; jj++) {
                int gcol = j * 32 + (tx << 1) + jj;
                S[i][jj] = (gcol > grow) ? -1e30f : S[i][jj] * scale;
            }
            // row max over this thread's 2 cols, then across 16 lanes
            float mloc = fmaxf(S[i][0], S[i][1]);
            #pragma unroll
            for (int s = 1; s <= 8; s <<= 1)
                mloc = fmaxf(mloc, __shfl_xor_sync(0xffffffffu, mloc, s));
            float m_new = fmaxf(m_i[i], mloc);
            float alpha = __expf(m_i[i] - m_new);
            float p0 = __expf(S[i][0] - m_new);
            float p1 = __expf(S[i][1] - m_new);
            float lloc = p0 + p1;
            #pragma unroll
            for (int s = 1; s <= 8; s <<= 1)
                lloc += __shfl_xor_sync(0xffffffffu, lloc, s);
            l_i[i] = l_i[i] * alpha + lloc;
            m_i[i] = m_new;
            // rescale O row
            #pragma unroll
            for (int jj = 0; jj < 4; jj++) O[i][jj] *= alpha;
            Ps[(ty << 2) + i][(tx << 1) + 0] = p0;
            Ps[(ty << 2) + i][(tx << 1) + 1] = p1;
        }
        __syncthreads();

        // O[4 rows][4 dims] += Ps[rows][0..31] @ Vs[0..31][dims]
        #pragma unroll 8
        for (int c = 0; c < 32; c++) {
            float p0 = Ps[(ty << 2) + 0][c];
            float p1 = Ps[(ty << 2) + 1][c];
            float p2 = Ps[(ty << 2) + 2][c];
            float p3 = Ps[(ty << 2) + 3][c];
            float v0 = Vs[c][(tx << 2) + 0];
            float v1 = Vs[c][(tx << 2) + 1];
            float v2 = Vs[c][(tx << 2) + 2];
            float v3 = Vs[c][(tx << 2) + 3];
            O[0][0] += p0 * v0; O[0][1] += p0 * v1; O[0][2] += p0 * v2; O[0][3] += p0 * v3;
            O[1][0] += p1 * v0; O[1][1] += p1 * v1; O[1][2] += p1 * v2; O[1][3] += p1 * v3;
            O[2][0] += p2 * v0; O[2][1] += p2 * v1; O[2][2] += p2 * v2; O[2][3] += p2 * v3;
            O[3][0] += p3 * v0; O[3][1] += p3 * v1; O[3][2] += p3 * v2; O[3][3] += p3 * v3;
        }
    }

    // Normalize and write out: out[b, t, h*64 + d]
    #pragma unroll
    for (int i = 0; i < 4; i++) {
        float inv_l = 1.0f / l_i[i];
        int t = qt * 64 + (ty << 2) + i;
        float4 v = make_float4(O[i][0] * inv_l, O[i][1] * inv_l,
                               O[i][2] * inv_l, O[i][3] * inv_l);
        *(float4*)&out[(size_t)(b * SEQ + t) * DM + h * DH + (tx << 2)] = v;
    }
}

extern "C" void kernel_launch(void* const* d_in, const int* in_sizes, int n_in,
                              void* d_out, int out_size)
{
    const float* X  = (const float*)d_in[0];
    const float* Wq = (const float*)d_in[1];
    const float* Wk = (const float*)d_in[2];
    const float* Wv = (const float*)d_in[3];
    float* out = (float*)d_out;

    // QKV projections: grid (N/64, M/64, 3)
    dim3 ggrid(DM / 64, MTOT / 64, 3);
    qkv_gemm_kernel<<<ggrid, 256>>>(X, Wq, Wk, Wv);

    // Attention: grid (qtiles, heads, batch)
    dim3 agrid(SEQ / 64, NH, BATCH);
    attn_kernel<<<agrid, 256>>>(out);
}

// round 3
// speedup vs baseline: 1.5576x; 1.5576x over previous
#include <cuda_runtime.h>
#include <cuda_bf16.h>
#include <cstdint>

#define BATCH 2
#define SEQ   2048
#define DM    1024
#define NH    16
#define DH    64
#define MTOT  (BATCH*SEQ)   // 4096

// Scratch for Q, K, V projections: [B*T, DM] each, fp32.
__device__ float g_Q[MTOT*DM];
__device__ float g_K[MTOT*DM];
__device__ float g_V[MTOT*DM];

// ---------------------------------------------------------------------------
// tf32 helpers (mma.sync — sm_80+ path, works on the non-'a' compute_103 build)
// ---------------------------------------------------------------------------
__device__ __forceinline__ uint32_t f2tf32(float f) {
    uint32_t r;
    asm("cvt.rna.tf32.f32 %0, %1;" : "=r"(r) : "f"(f));
    return r;
}

__device__ __forceinline__ void mma_tf32_16x8x8(float* c, const uint32_t* a, const uint32_t* b) {
    asm volatile(
        "mma.sync.aligned.m16n8k8.row.col.f32.tf32.tf32.f32 "
        "{%0,%1,%2,%3}, {%4,%5,%6,%7}, {%8,%9}, {%0,%1,%2,%3};"
        : "+f"(c[0]), "+f"(c[1]), "+f"(c[2]), "+f"(c[3])
        : "r"(a[0]), "r"(a[1]), "r"(a[2]), "r"(a[3]), "r"(b[0]), "r"(b[1]));
}

// ---------------------------------------------------------------------------
// QKV projection via tf32 mma.sync.
// Block tile 128(M) x 128(N), K chunk 32. 256 threads = 8 warps in 2(m) x 4(n);
// each warp owns 64x32 via 4x4 grid of m16n8k8 tiles.
// Y[m,n] = sum_k X[m,k] * W[n,k]   (A=X row-major, B[k][n]=W[n][k] "col" layout)
// Smem: [row][k] with k-stride 36 -> bank = (4*row + k) % 32, conflict-free
// for fragment loads (8 rows x 4 k-cols per quarter-group pattern).
// ---------------------------------------------------------------------------
#define KT 32
#define KSTR 36

__global__ __launch_bounds__(256) void qkv_gemm_mma(
    const float* __restrict__ X,
    const float* __restrict__ Wq,
    const float* __restrict__ Wk,
    const float* __restrict__ Wv)
{
    __shared__ uint32_t Xs[128][KSTR];
    __shared__ uint32_t Ws[128][KSTR];

    const float* W;
    float* Y;
    if (blockIdx.z == 0)      { W = Wq; Y = g_Q; }
    else if (blockIdx.z == 1) { W = Wk; Y = g_K; }
    else                      { W = Wv; Y = g_V; }

    const int m0 = blockIdx.y * 128;
    const int n0 = blockIdx.x * 128;
    const int tid  = threadIdx.x;
    const int wid  = tid >> 5;
    const int lane = tid & 31;
    const int wm = wid >> 2;          // 0..1 -> 64 rows each
    const int wn = wid & 3;           // 0..3 -> 32 cols each
    const int g   = lane >> 2;        // group id 0..7
    const int tig = lane & 3;         // thread-in-group 0..3

    const int lr  = tid >> 3;         // 0..31 loader row
    const int lc4 = (tid & 7) << 2;   // 0,4,..,28 loader k col

    float acc[4][4][4] = {};          // [mt][nt][reg]

    for (int kc = 0; kc < DM / KT; kc++) {
        const int k0 = kc * KT;
        // Load X[128x32], W[128x32] -> smem, converting to tf32 bits.
        #pragma unroll
        for (int rep = 0; rep < 4; rep++) {
            int row = lr + rep * 32;
            float4 xv = *(const float4*)&X[(size_t)(m0 + row) * DM + k0 + lc4];
            Xs[row][lc4 + 0] = f2tf32(xv.x); Xs[row][lc4 + 1] = f2tf32(xv.y);
            Xs[row][lc4 + 2] = f2tf32(xv.z); Xs[row][lc4 + 3] = f2tf32(xv.w);
            float4 wv = *(const float4*)&W[(size_t)(n0 + row) * DM + k0 + lc4];
            Ws[row][lc4 + 0] = f2tf32(wv.x); Ws[row][lc4 + 1] = f2tf32(wv.y);
            Ws[row][lc4 + 2] = f2tf32(wv.z); Ws[row][lc4 + 3] = f2tf32(wv.w);
        }
        __syncthreads();

        #pragma unroll
        for (int ks = 0; ks < 4; ks++) {
            const int kk = ks * 8;
            uint32_t a[4][4];
            #pragma unroll
            for (int mt = 0; mt < 4; mt++) {
                int mb = wm * 64 + mt * 16;
                a[mt][0] = Xs[mb + g    ][kk + tig    ];
                a[mt][1] = Xs[mb + g + 8][kk + tig    ];
                a[mt][2] = Xs[mb + g    ][kk + tig + 4];
                a[mt][3] = Xs[mb + g + 8][kk + tig + 4];
            }
            uint32_t b[4][2];
            #pragma unroll
            for (int nt = 0; nt < 4; nt++) {
                int nb = wn * 32 + nt * 8 + g;
                b[nt][0] = Ws[nb][kk + tig    ];
                b[nt][1] = Ws[nb][kk + tig + 4];
            }
            #pragma unroll
            for (int mt = 0; mt < 4; mt++)
                #pragma unroll
                for (int nt = 0; nt < 4; nt++)
                    mma_tf32_16x8x8(acc[mt][nt], a[mt], b[nt]);
        }
        __syncthreads();
    }

    // Epilogue: c0,c1 at (row, col..col+1); c2,c3 at (row+8, col..col+1)
    #pragma unroll
    for (int mt = 0; mt < 4; mt++) {
        int row = m0 + wm * 64 + mt * 16 + g;
        #pragma unroll
        for (int nt = 0; nt < 4; nt++) {
            int col = n0 + wn * 32 + nt * 8 + tig * 2;
            *(float2*)&Y[(size_t)row * DM + col]       = make_float2(acc[mt][nt][0], acc[mt][nt][1]);
            *(float2*)&Y[(size_t)(row + 8) * DM + col] = make_float2(acc[mt][nt][2], acc[mt][nt][3]);
        }
    }
}

// ---------------------------------------------------------------------------
// Flash-style causal attention (fp32, vectorized LDS).
// Grid: (SEQ/64, NH, BATCH). 256 threads. Row stride 68 keeps float4 align.
// ---------------------------------------------------------------------------
#define QSTR 68
#define DOT4(s, a, b) { s += (a).x*(b).x; s += (a).y*(b).y; s += (a).z*(b).z; s += (a).w*(b).w; }

__global__ __launch_bounds__(256) void attn_kernel(float* __restrict__ out)
{
    const int qt = blockIdx.x;
    const int h  = blockIdx.y;
    const int b  = blockIdx.z;

    __shared__ float Qs[64][QSTR];
    __shared__ float Ks[32][QSTR];
    __shared__ float Vs[32][QSTR];
    __shared__ float Ps[64][33];

    const int tid = threadIdx.x;
    const int tx = tid & 15;
    const int ty = tid >> 4;

    const float* Qg = g_Q + (size_t)b * SEQ * DM + (size_t)h * DH;
    const float* Kg = g_K + (size_t)b * SEQ * DM + (size_t)h * DH;
    const float* Vg = g_V + (size_t)b * SEQ * DM + (size_t)h * DH;

    for (int i = tid; i < 64 * 16; i += 256) {
        int r  = i >> 4;
        int c4 = (i & 15) << 2;
        float4 v = *(const float4*)&Qg[(size_t)(qt * 64 + r) * DM + c4];
        *(float4*)&Qs[r][c4] = v;
    }

    float m_i[4], l_i[4];
    float O[4][4] = {};
    #pragma unroll
    for (int i = 0; i < 4; i++) { m_i[i] = -1e30f; l_i[i] = 0.0f; }

    const float scale = 0.125f;               // 1/sqrt(64)
    const int jmax = 2 * qt + 1;

    for (int j = 0; j <= jmax; j++) {
        __syncthreads();
        for (int i = tid; i < 32 * 16; i += 256) {
            int r  = i >> 4;
            int c4 = (i & 15) << 2;
            float4 kv = *(const float4*)&Kg[(size_t)(j * 32 + r) * DM + c4];
            *(float4*)&Ks[r][c4] = kv;
            float4 vv = *(const float4*)&Vg[(size_t)(j * 32 + r) * DM + c4];
            *(float4*)&Vs[r][c4] = vv;
        }
        __syncthreads();

        float S[4][2] = {};
        #pragma unroll
        for (int k4 = 0; k4 < 16; k4++) {
            float4 a0 = *(const float4*)&Qs[(ty << 2) + 0][k4 << 2];
            float4 a1 = *(const float4*)&Qs[(ty << 2) + 1][k4 << 2];
            float4 a2 = *(const float4*)&Qs[(ty << 2) + 2][k4 << 2];
            float4 a3 = *(const float4*)&Qs[(ty << 2) + 3][k4 << 2];
            float4 b0 = *(const float4*)&Ks[(tx << 1) + 0][k4 << 2];
            float4 b1 = *(const float4*)&Ks[(tx << 1) + 1][k4 << 2];
            DOT4(S[0][0], a0, b0); DOT4(S[0][1], a0, b1);
            DOT4(S[1][0], a1, b0); DOT4(S[1][1], a1, b1);
            DOT4(S[2][0], a2, b0); DOT4(S[2][1], a2, b1);
            DOT4(S[3][0], a3, b0); DOT4(S[3][1], a3, b1);
        }

        #pragma unroll
        for (int i = 0; i < 4; i++) {
            int grow = qt * 64 + (ty << 2) + i;
            #pragma unroll
            for (int jj = 0; jj < 2; jj++) {
                int gcol = j * 32 + (tx << 1) + jj;
                S[i][jj] = (gcol > grow) ? -1e30f : S[i][jj] * scale;
            }
            float mloc = fmaxf(S[i][0], S[i][1]);
            #pragma unroll
            for (int s = 1; s <= 8; s <<= 1)
                mloc = fmaxf(mloc, __shfl_xor_sync(0xffffffffu, mloc, s));
            float m_new = fmaxf(m_i[i], mloc);
            float alpha = __expf(m_i[i] - m_new);
            float p0 = __expf(S[i][0] - m_new);
            float p1 = __expf(S[i][1] - m_new);
            float lloc = p0 + p1;
            #pragma unroll
            for (int s = 1; s <= 8; s <<= 1)
                lloc += __shfl_xor_sync(0xffffffffu, lloc, s);
            l_i[i] = l_i[i] * alpha + lloc;
            m_i[i] = m_new;
            #pragma unroll
            for (int jj = 0; jj < 4; jj++) O[i][jj] *= alpha;
            Ps[(ty << 2) + i][(tx << 1) + 0] = p0;
            Ps[(ty << 2) + i][(tx << 1) + 1] = p1;
        }
        __syncthreads();

        #pragma unroll 8
        for (int c = 0; c < 32; c++) {
            float p0 = Ps[(ty << 2) + 0][c];
            float p1 = Ps[(ty << 2) + 1][c];
            float p2 = Ps[(ty << 2) + 2][c];
            float p3 = Ps[(ty << 2) + 3][c];
            float4 v = *(const float4*)&Vs[c][tx << 2];
            O[0][0] += p0 * v.x; O[0][1] += p0 * v.y; O[0][2] += p0 * v.z; O[0][3] += p0 * v.w;
            O[1][0] += p1 * v.x; O[1][1] += p1 * v.y; O[1][2] += p1 * v.z; O[1][3] += p1 * v.w;
            O[2][0] += p2 * v.x; O[2][1] += p2 * v.y; O[2][2] += p2 * v.z; O[2][3] += p2 * v.w;
            O[3][0] += p3 * v.x; O[3][1] += p3 * v.y; O[3][2] += p3 * v.z; O[3][3] += p3 * v.w;
        }
    }

    #pragma unroll
    for (int i = 0; i < 4; i++) {
        float inv_l = 1.0f / l_i[i];
        int t = qt * 64 + (ty << 2) + i;
        float4 v = make_float4(O[i][0] * inv_l, O[i][1] * inv_l,
                               O[i][2] * inv_l, O[i][3] * inv_l);
        *(float4*)&out[(size_t)(b * SEQ + t) * DM + h * DH + (tx << 2)] = v;
    }
}

extern "C" void kernel_launch(void* const* d_in, const int* in_sizes, int n_in,
                              void* d_out, int out_size)
{
    const float* X  = (const float*)d_in[0];
    const float* Wq = (const float*)d_in[1];
    const float* Wk = (const float*)d_in[2];
    const float* Wv = (const float*)d_in[3];
    float* out = (float*)d_out;

    dim3 ggrid(DM / 128, MTOT / 128, 3);
    qkv_gemm_mma<<<ggrid, 256>>>(X, Wq, Wk, Wv);

    dim3 agrid(SEQ / 64, NH, BATCH);
    attn_kernel<<<agrid, 256>>>(out);
}

// round 4
// speedup vs baseline: 3.9974x; 2.5664x over previous
#include <cuda_runtime.h>
#include <cuda_fp16.h>
#include <cuda_bf16.h>
#include <cstdint>

#define BATCH 2
#define SEQ   2048
#define DM    1024
#define NH    16
#define DH    64
#define MTOT  (BATCH*SEQ)   // 4096

// Scratch for Q, K, V projections: [B*T, DM] each, fp32.
__device__ float g_Q[MTOT*DM];
__device__ float g_K[MTOT*DM];
__device__ float g_V[MTOT*DM];

// ---------------------------------------------------------------------------
// tf32 helpers (mma.sync — sm_80+ path, works on the non-'a' compute_103 build)
// ---------------------------------------------------------------------------
__device__ __forceinline__ uint32_t f2tf32(float f) {
    uint32_t r;
    asm("cvt.rna.tf32.f32 %0, %1;" : "=r"(r) : "f"(f));
    return r;
}

__device__ __forceinline__ void mma_tf32_16x8x8(float* c, const uint32_t* a, const uint32_t* b) {
    asm volatile(
        "mma.sync.aligned.m16n8k8.row.col.f32.tf32.tf32.f32 "
        "{%0,%1,%2,%3}, {%4,%5,%6,%7}, {%8,%9}, {%0,%1,%2,%3};"
        : "+f"(c[0]), "+f"(c[1]), "+f"(c[2]), "+f"(c[3])
        : "r"(a[0]), "r"(a[1]), "r"(a[2]), "r"(a[3]), "r"(b[0]), "r"(b[1]));
}

// fp16 mma m16n8k16, f32 accumulate
__device__ __forceinline__ void mma_f16_16x8x16(float* c, const uint32_t* a, uint32_t b0, uint32_t b1) {
    asm volatile(
        "mma.sync.aligned.m16n8k16.row.col.f32.f16.f16.f32 "
        "{%0,%1,%2,%3}, {%4,%5,%6,%7}, {%8,%9}, {%0,%1,%2,%3};"
        : "+f"(c[0]), "+f"(c[1]), "+f"(c[2]), "+f"(c[3])
        : "r"(a[0]), "r"(a[1]), "r"(a[2]), "r"(a[3]), "r"(b0), "r"(b1));
}

__device__ __forceinline__ uint32_t pack_h2(float lo, float hi) {
    __half2 h = __floats2half2_rn(lo, hi);
    return *(uint32_t*)&h;
}

// ---------------------------------------------------------------------------
// QKV projection via tf32 mma.sync (unchanged from R3 — proven).
// ---------------------------------------------------------------------------
#define KT 32
#define KSTR 36

__global__ __launch_bounds__(256) void qkv_gemm_mma(
    const float* __restrict__ X,
    const float* __restrict__ Wq,
    const float* __restrict__ Wk,
    const float* __restrict__ Wv)
{
    __shared__ uint32_t Xs[128][KSTR];
    __shared__ uint32_t Ws[128][KSTR];

    const float* W;
    float* Y;
    if (blockIdx.z == 0)      { W = Wq; Y = g_Q; }
    else if (blockIdx.z == 1) { W = Wk; Y = g_K; }
    else                      { W = Wv; Y = g_V; }

    const int m0 = blockIdx.y * 128;
    const int n0 = blockIdx.x * 128;
    const int tid  = threadIdx.x;
    const int wid  = tid >> 5;
    const int lane = tid & 31;
    const int wm = wid >> 2;
    const int wn = wid & 3;
    const int g   = lane >> 2;
    const int tig = lane & 3;

    const int lr  = tid >> 3;
    const int lc4 = (tid & 7) << 2;

    float acc[4][4][4] = {};

    for (int kc = 0; kc < DM / KT; kc++) {
        const int k0 = kc * KT;
        #pragma unroll
        for (int rep = 0; rep < 4; rep++) {
            int row = lr + rep * 32;
            float4 xv = *(const float4*)&X[(size_t)(m0 + row) * DM + k0 + lc4];
            Xs[row][lc4 + 0] = f2tf32(xv.x); Xs[row][lc4 + 1] = f2tf32(xv.y);
            Xs[row][lc4 + 2] = f2tf32(xv.z); Xs[row][lc4 + 3] = f2tf32(xv.w);
            float4 wv = *(const float4*)&W[(size_t)(n0 + row) * DM + k0 + lc4];
            Ws[row][lc4 + 0] = f2tf32(wv.x); Ws[row][lc4 + 1] = f2tf32(wv.y);
            Ws[row][lc4 + 2] = f2tf32(wv.z); Ws[row][lc4 + 3] = f2tf32(wv.w);
        }
        __syncthreads();

        #pragma unroll
        for (int ks = 0; ks < 4; ks++) {
            const int kk = ks * 8;
            uint32_t a[4][4];
            #pragma unroll
            for (int mt = 0; mt < 4; mt++) {
                int mb = wm * 64 + mt * 16;
                a[mt][0] = Xs[mb + g    ][kk + tig    ];
                a[mt][1] = Xs[mb + g + 8][kk + tig    ];
                a[mt][2] = Xs[mb + g    ][kk + tig + 4];
                a[mt][3] = Xs[mb + g + 8][kk + tig + 4];
            }
            uint32_t b[4][2];
            #pragma unroll
            for (int nt = 0; nt < 4; nt++) {
                int nb = wn * 32 + nt * 8 + g;
                b[nt][0] = Ws[nb][kk + tig    ];
                b[nt][1] = Ws[nb][kk + tig + 4];
            }
            #pragma unroll
            for (int mt = 0; mt < 4; mt++)
                #pragma unroll
                for (int nt = 0; nt < 4; nt++)
                    mma_tf32_16x8x8(acc[mt][nt], a[mt], b[nt]);
        }
        __syncthreads();
    }

    #pragma unroll
    for (int mt = 0; mt < 4; mt++) {
        int row = m0 + wm * 64 + mt * 16 + g;
        #pragma unroll
        for (int nt = 0; nt < 4; nt++) {
            int col = n0 + wn * 32 + nt * 8 + tig * 2;
            *(float2*)&Y[(size_t)row * DM + col]       = make_float2(acc[mt][nt][0], acc[mt][nt][1]);
            *(float2*)&Y[(size_t)(row + 8) * DM + col] = make_float2(acc[mt][nt][2], acc[mt][nt][3]);
        }
    }
}

// ---------------------------------------------------------------------------
// Tensor-core flash attention (fp16 mma.sync, fp32 accum).
// Grid: (SEQ/128, NH, BATCH) = (16,16,2). 256 threads = 8 warps.
// Warp w owns Q rows [qt*128 + 16w, +16). KV tiles of 64.
// Smem: Ks[kv][d], Vt[d][kv] (transposed), Ps[warp][16][64] — all half,
// row stride 72 halves -> conflict-free fragment LDS.
// ---------------------------------------------------------------------------
#define HSTR 72

__global__ __launch_bounds__(256) void attn_tc(float* __restrict__ out)
{
    const int qt = blockIdx.x;
    const int h  = blockIdx.y;
    const int b  = blockIdx.z;

    __shared__ __half Ks[64][HSTR];
    __shared__ __half Vt[64][HSTR];
    __shared__ __half Ps[8][16][HSTR];

    const int tid  = threadIdx.x;
    const int w    = tid >> 5;
    const int lane = tid & 31;
    const int g    = lane >> 2;
    const int tig  = lane & 3;
    const int qb   = qt * 128 + w * 16;   // warp's first Q row

    const float* Qg = g_Q + (size_t)b * SEQ * DM + (size_t)h * DH;
    const float* Kg = g_K + (size_t)b * SEQ * DM + (size_t)h * DH;
    const float* Vg = g_V + (size_t)b * SEQ * DM + (size_t)h * DH;

    // Q fragments, scale 1/sqrt(64)=0.125 folded in. qa[ks][0..3]
    uint32_t qa[4][4];
    {
        const float s = 0.125f;
        #pragma unroll
        for (int ks = 0; ks < 4; ks++) {
            int c = ks * 16 + tig * 2;
            float2 v0 = *(const float2*)&Qg[(size_t)(qb + g    ) * DM + c];
            float2 v1 = *(const float2*)&Qg[(size_t)(qb + g + 8) * DM + c];
            float2 v2 = *(const float2*)&Qg[(size_t)(qb + g    ) * DM + c + 8];
            float2 v3 = *(const float2*)&Qg[(size_t)(qb + g + 8) * DM + c + 8];
            qa[ks][0] = pack_h2(v0.x * s, v0.y * s);
            qa[ks][1] = pack_h2(v1.x * s, v1.y * s);
            qa[ks][2] = pack_h2(v2.x * s, v2.y * s);
            qa[ks][3] = pack_h2(v3.x * s, v3.y * s);
        }
    }

    float m0 = -1e30f, m1 = -1e30f, l0 = 0.0f, l1 = 0.0f;
    float O[8][4] = {};

    const int jmax = 2 * qt + 1;

    for (int j = 0; j <= jmax; j++) {
        __syncthreads();   // prior iter done reading Ks/Vt
        // Load K tile: 64 rows x 64 dims -> half. One row-quarter per thread.
        {
            int r  = tid >> 2;
            int c0 = (tid & 3) * 16;
            const float* src = &Kg[(size_t)(j * 64 + r) * DM + c0];
            float4 f0 = *(const float4*)(src);
            float4 f1 = *(const float4*)(src + 4);
            float4 f2 = *(const float4*)(src + 8);
            float4 f3 = *(const float4*)(src + 12);
            uint32_t* dst = (uint32_t*)&Ks[r][c0];
            dst[0] = pack_h2(f0.x, f0.y); dst[1] = pack_h2(f0.z, f0.w);
            dst[2] = pack_h2(f1.x, f1.y); dst[3] = pack_h2(f1.z, f1.w);
            dst[4] = pack_h2(f2.x, f2.y); dst[5] = pack_h2(f2.z, f2.w);
            dst[6] = pack_h2(f3.x, f3.y); dst[7] = pack_h2(f3.z, f3.w);
        }
        // Load V tile transposed: Vt[d][kv]
        #pragma unroll
        for (int it = 0; it < 4; it++) {
            int idx = tid + it * 256;
            int kv  = idx & 63;
            int c4  = (idx >> 6) * 4;
            float4 v = *(const float4*)&Vg[(size_t)(j * 64 + kv) * DM + c4];
            Vt[c4 + 0][kv] = __float2half(v.x);
            Vt[c4 + 1][kv] = __float2half(v.y);
            Vt[c4 + 2][kv] = __float2half(v.z);
            Vt[c4 + 3][kv] = __float2half(v.w);
        }
        __syncthreads();

        if (j * 64 <= qb + 15) {     // warp has at least one unmasked column
            // S = Q K^T  (16 x 64 per warp)
            float S[8][4] = {};
            #pragma unroll
            for (int ks = 0; ks < 4; ks++) {
                int c = ks * 16 + tig * 2;
                #pragma unroll
                for (int nt = 0; nt < 8; nt++) {
                    uint32_t b0 = *(const uint32_t*)&Ks[nt * 8 + g][c];
                    uint32_t b1 = *(const uint32_t*)&Ks[nt * 8 + g][c + 8];
                    mma_f16_16x8x16(S[nt], qa[ks], b0, b1);
                }
            }

            // causal mask (only diagonal-straddling tiles need it)
            if (j >= 2 * qt) {
                #pragma unroll
                for (int nt = 0; nt < 8; nt++) {
                    int colb = j * 64 + nt * 8 + tig * 2;
                    int r0 = qb + g, r1 = qb + g + 8;
                    if (colb     > r0) S[nt][0] = -1e30f;
                    if (colb + 1 > r0) S[nt][1] = -1e30f;
                    if (colb     > r1) S[nt][2] = -1e30f;
                    if (colb + 1 > r1) S[nt][3] = -1e30f;
                }
            }

            // online softmax: rows g (S[.][0..1]) and g+8 (S[.][2..3])
            float mx0 = -1e30f, mx1 = -1e30f;
            #pragma unroll
            for (int nt = 0; nt < 8; nt++) {
                mx0 = fmaxf(mx0, fmaxf(S[nt][0], S[nt][1]));
                mx1 = fmaxf(mx1, fmaxf(S[nt][2], S[nt][3]));
            }
            mx0 = fmaxf(mx0, __shfl_xor_sync(0xffffffffu, mx0, 1));
            mx0 = fmaxf(mx0, __shfl_xor_sync(0xffffffffu, mx0, 2));
            mx1 = fmaxf(mx1, __shfl_xor_sync(0xffffffffu, mx1, 1));
            mx1 = fmaxf(mx1, __shfl_xor_sync(0xffffffffu, mx1, 2));

            float mn0 = fmaxf(m0, mx0), mn1 = fmaxf(m1, mx1);
            float al0 = __expf(m0 - mn0), al1 = __expf(m1 - mn1);
            float s0 = 0.0f, s1 = 0.0f;
            #pragma unroll
            for (int nt = 0; nt < 8; nt++) {
                S[nt][0] = __expf(S[nt][0] - mn0); s0 += S[nt][0];
                S[nt][1] = __expf(S[nt][1] - mn0); s0 += S[nt][1];
                S[nt][2] = __expf(S[nt][2] - mn1); s1 += S[nt][2];
                S[nt][3] = __expf(S[nt][3] - mn1); s1 += S[nt][3];
            }
            s0 += __shfl_xor_sync(0xffffffffu, s0, 1);
            s0 += __shfl_xor_sync(0xffffffffu, s0, 2);
            s1 += __shfl_xor_sync(0xffffffffu, s1, 1);
            s1 += __shfl_xor_sync(0xffffffffu, s1, 2);
            l0 = l0 * al0 + s0;  l1 = l1 * al1 + s1;
            m0 = mn0;            m1 = mn1;

            #pragma unroll
            for (int nt = 0; nt < 8; nt++) {
                O[nt][0] *= al0; O[nt][1] *= al0;
                O[nt][2] *= al1; O[nt][3] *= al1;
            }

            // P -> smem (half), re-fragment for PV
            #pragma unroll
            for (int nt = 0; nt < 8; nt++) {
                *(uint32_t*)&Ps[w][g    ][nt * 8 + tig * 2] = pack_h2(S[nt][0], S[nt][1]);
                *(uint32_t*)&Ps[w][g + 8][nt * 8 + tig * 2] = pack_h2(S[nt][2], S[nt][3]);
            }
            __syncwarp();

            // O += P V   (k = kv, 4 k-steps of 16)
            #pragma unroll
            for (int ks = 0; ks < 4; ks++) {
                int c = ks * 16 + tig * 2;
                uint32_t a[4];
                a[0] = *(const uint32_t*)&Ps[w][g    ][c];
                a[1] = *(const uint32_t*)&Ps[w][g + 8][c];
                a[2] = *(const uint32_t*)&Ps[w][g    ][c + 8];
                a[3] = *(const uint32_t*)&Ps[w][g + 8][c + 8];
                #pragma unroll
                for (int nt = 0; nt < 8; nt++) {
                    uint32_t b0 = *(const uint32_t*)&Vt[nt * 8 + g][c];
                    uint32_t b1 = *(const uint32_t*)&Vt[nt * 8 + g][c + 8];
                    mma_f16_16x8x16(O[nt], a, b0, b1);
                }
            }
        }
    }

    // epilogue
    float inv0 = 1.0f / l0, inv1 = 1.0f / l1;
    #pragma unroll
    for (int nt = 0; nt < 8; nt++) {
        int col = h * DH + nt * 8 + tig * 2;
        int r0 = qb + g, r1 = qb + g + 8;
        *(float2*)&out[(size_t)(b * SEQ + r0) * DM + col] =
            make_float2(O[nt][0] * inv0, O[nt][1] * inv0);
        *(float2*)&out[(size_t)(b * SEQ + r1) * DM + col] =
            make_float2(O[nt][2] * inv1, O[nt][3] * inv1);
    }
}

extern "C" void kernel_launch(void* const* d_in, const int* in_sizes, int n_in,
                              void* d_out, int out_size)
{
    const float* X  = (const float*)d_in[0];
    const float* Wq = (const float*)d_in[1];
    const float* Wk = (const float*)d_in[2];
    const float* Wv = (const float*)d_in[3];
    float* out = (float*)d_out;

    dim3 ggrid(DM / 128, MTOT / 128, 3);
    qkv_gemm_mma<<<ggrid, 256>>>(X, Wq, Wk, Wv);

    dim3 agrid(SEQ / 128, NH, BATCH);
    attn_tc<<<agrid, 256>>>(out);
}

// round 5
// speedup vs baseline: 5.5255x; 1.3823x over previous
#include <cuda_runtime.h>
#include <cuda_fp16.h>
#include <cuda_bf16.h>
#include <cstdint>

#define BATCH 2
#define SEQ   2048
#define DM    1024
#define NH    16
#define DH    64
#define MTOT  (BATCH*SEQ)   // 4096

// Scratch for Q, K, V projections: [B*T, DM] each, fp32.
__device__ float g_Q[MTOT*DM];
__device__ float g_K[MTOT*DM];
__device__ float g_V[MTOT*DM];

// fp16 mma m16n8k16, f32 accumulate
__device__ __forceinline__ void mma_f16_16x8x16(float* c, const uint32_t* a, uint32_t b0, uint32_t b1) {
    asm volatile(
        "mma.sync.aligned.m16n8k16.row.col.f32.f16.f16.f32 "
        "{%0,%1,%2,%3}, {%4,%5,%6,%7}, {%8,%9}, {%0,%1,%2,%3};"
        : "+f"(c[0]), "+f"(c[1]), "+f"(c[2]), "+f"(c[3])
        : "r"(a[0]), "r"(a[1]), "r"(a[2]), "r"(a[3]), "r"(b0), "r"(b1));
}

__device__ __forceinline__ uint32_t pack_h2(float lo, float hi) {
    __half2 h = __floats2half2_rn(lo, hi);
    return *(uint32_t*)&h;
}

// ---------------------------------------------------------------------------
// QKV projection via fp16 mma.sync (fp32 accumulate).
// Block tile 128(M) x 128(N), K chunk 32. 8 warps in 2(m) x 4(n), each warp
// 64x32 via 4x4 m16n8k16 tiles, 2 k-steps per chunk.
// Smem: packed half2 along k, row stride 20 u32 (16 data + 4 pad).
// ---------------------------------------------------------------------------
#define KT 32
#define KS2 20

__global__ __launch_bounds__(256) void qkv_gemm_h(
    const float* __restrict__ X,
    const float* __restrict__ Wq,
    const float* __restrict__ Wk,
    const float* __restrict__ Wv)
{
    __shared__ uint32_t Xs[128][KS2];
    __shared__ uint32_t Ws[128][KS2];

    const float* W;
    float* Y;
    if (blockIdx.z == 0)      { W = Wq; Y = g_Q; }
    else if (blockIdx.z == 1) { W = Wk; Y = g_K; }
    else                      { W = Wv; Y = g_V; }

    const int m0 = blockIdx.y * 128;
    const int n0 = blockIdx.x * 128;
    const int tid  = threadIdx.x;
    const int wid  = tid >> 5;
    const int lane = tid & 31;
    const int wm = wid >> 2;          // 0..1
    const int wn = wid & 3;           // 0..3
    const int g   = lane >> 2;        // 0..7
    const int tig = lane & 3;         // 0..3

    const int lr  = tid >> 3;         // 0..31 loader row
    const int lc4 = (tid & 7) << 2;   // 0,4,..,28 k col (floats)

    float acc[4][4][4] = {};

    for (int kc = 0; kc < DM / KT; kc++) {
        const int k0 = kc * KT;
        #pragma unroll
        for (int rep = 0; rep < 4; rep++) {
            int row = lr + rep * 32;
            float4 xv = *(const float4*)&X[(size_t)(m0 + row) * DM + k0 + lc4];
            Xs[row][(lc4 >> 1) + 0] = pack_h2(xv.x, xv.y);
            Xs[row][(lc4 >> 1) + 1] = pack_h2(xv.z, xv.w);
            float4 wv = *(const float4*)&W[(size_t)(n0 + row) * DM + k0 + lc4];
            Ws[row][(lc4 >> 1) + 0] = pack_h2(wv.x, wv.y);
            Ws[row][(lc4 >> 1) + 1] = pack_h2(wv.z, wv.w);
        }
        __syncthreads();

        #pragma unroll
        for (int ks = 0; ks < 2; ks++) {
            const int kk = ks * 8;    // u32 (half2) offset
            uint32_t a[4][4];
            #pragma unroll
            for (int mt = 0; mt < 4; mt++) {
                int mb = wm * 64 + mt * 16;
                a[mt][0] = Xs[mb + g    ][kk + tig    ];
                a[mt][1] = Xs[mb + g + 8][kk + tig    ];
                a[mt][2] = Xs[mb + g    ][kk + tig + 4];
                a[mt][3] = Xs[mb + g + 8][kk + tig + 4];
            }
            uint32_t b[4][2];
            #pragma unroll
            for (int nt = 0; nt < 4; nt++) {
                int nb = wn * 32 + nt * 8 + g;
                b[nt][0] = Ws[nb][kk + tig    ];
                b[nt][1] = Ws[nb][kk + tig + 4];
            }
            #pragma unroll
            for (int mt = 0; mt < 4; mt++)
                #pragma unroll
                for (int nt = 0; nt < 4; nt++)
                    mma_f16_16x8x16(acc[mt][nt], a[mt], b[nt][0], b[nt][1]);
        }
        __syncthreads();
    }

    #pragma unroll
    for (int mt = 0; mt < 4; mt++) {
        int row = m0 + wm * 64 + mt * 16 + g;
        #pragma unroll
        for (int nt = 0; nt < 4; nt++) {
            int col = n0 + wn * 32 + nt * 8 + tig * 2;
            *(float2*)&Y[(size_t)row * DM + col]       = make_float2(acc[mt][nt][0], acc[mt][nt][1]);
            *(float2*)&Y[(size_t)(row + 8) * DM + col] = make_float2(acc[mt][nt][2], acc[mt][nt][3]);
        }
    }
}

// ---------------------------------------------------------------------------
// Tensor-core flash attention (fp16 mma.sync, fp32 accum), work-paired.
// Grid: (8, NH, BATCH) = 256 CTAs. Each CTA does Q tiles qa and 15-qa
// sequentially -> uniform 34 KV tiles per CTA, one balanced wave.
// ---------------------------------------------------------------------------
#define HSTR 72
#define NQT  (SEQ / 128)   // 16

__global__ __launch_bounds__(256) void attn_tc(float* __restrict__ out)
{
    const int qa = blockIdx.x;
    const int h  = blockIdx.y;
    const int b  = blockIdx.z;

    __shared__ __half Ks[64][HSTR];
    __shared__ __half Vt[64][HSTR];
    __shared__ __half Ps[8][16][HSTR];

    const int tid  = threadIdx.x;
    const int w    = tid >> 5;
    const int lane = tid & 31;
    const int g    = lane >> 2;
    const int tig  = lane & 3;

    const float* Qg = g_Q + (size_t)b * SEQ * DM + (size_t)h * DH;
    const float* Kg = g_K + (size_t)b * SEQ * DM + (size_t)h * DH;
    const float* Vg = g_V + (size_t)b * SEQ * DM + (size_t)h * DH;

    #pragma unroll 1
    for (int phase = 0; phase < 2; phase++) {
        const int qt = phase ? (NQT - 1 - qa) : qa;
        const int qb = qt * 128 + w * 16;

        // Q fragments, scale 1/8 folded in.
        uint32_t qa_f[4][4];
        {
            const float s = 0.125f;
            #pragma unroll
            for (int ks = 0; ks < 4; ks++) {
                int c = ks * 16 + tig * 2;
                float2 v0 = *(const float2*)&Qg[(size_t)(qb + g    ) * DM + c];
                float2 v1 = *(const float2*)&Qg[(size_t)(qb + g + 8) * DM + c];
                float2 v2 = *(const float2*)&Qg[(size_t)(qb + g    ) * DM + c + 8];
                float2 v3 = *(const float2*)&Qg[(size_t)(qb + g + 8) * DM + c + 8];
                qa_f[ks][0] = pack_h2(v0.x * s, v0.y * s);
                qa_f[ks][1] = pack_h2(v1.x * s, v1.y * s);
                qa_f[ks][2] = pack_h2(v2.x * s, v2.y * s);
                qa_f[ks][3] = pack_h2(v3.x * s, v3.y * s);
            }
        }

        float m0 = -1e30f, m1 = -1e30f, l0 = 0.0f, l1 = 0.0f;
        float O[8][4] = {};

        const int jmax = 2 * qt + 1;

        for (int j = 0; j <= jmax; j++) {
            __syncthreads();
            {   // K tile 64x64 -> half
                int r  = tid >> 2;
                int c0 = (tid & 3) * 16;
                const float* src = &Kg[(size_t)(j * 64 + r) * DM + c0];
                float4 f0 = *(const float4*)(src);
                float4 f1 = *(const float4*)(src + 4);
                float4 f2 = *(const float4*)(src + 8);
                float4 f3 = *(const float4*)(src + 12);
                uint32_t* dst = (uint32_t*)&Ks[r][c0];
                dst[0] = pack_h2(f0.x, f0.y); dst[1] = pack_h2(f0.z, f0.w);
                dst[2] = pack_h2(f1.x, f1.y); dst[3] = pack_h2(f1.z, f1.w);
                dst[4] = pack_h2(f2.x, f2.y); dst[5] = pack_h2(f2.z, f2.w);
                dst[6] = pack_h2(f3.x, f3.y); dst[7] = pack_h2(f3.z, f3.w);
            }
            #pragma unroll
            for (int it = 0; it < 4; it++) {   // V transposed
                int idx = tid + it * 256;
                int kv  = idx & 63;
                int c4  = (idx >> 6) * 4;
                float4 v = *(const float4*)&Vg[(size_t)(j * 64 + kv) * DM + c4];
                Vt[c4 + 0][kv] = __float2half(v.x);
                Vt[c4 + 1][kv] = __float2half(v.y);
                Vt[c4 + 2][kv] = __float2half(v.z);
                Vt[c4 + 3][kv] = __float2half(v.w);
            }
            __syncthreads();

            if (j * 64 <= qb + 15) {
                float S[8][4] = {};
                #pragma unroll
                for (int ks = 0; ks < 4; ks++) {
                    int c = ks * 16 + tig * 2;
                    #pragma unroll
                    for (int nt = 0; nt < 8; nt++) {
                        uint32_t b0 = *(const uint32_t*)&Ks[nt * 8 + g][c];
                        uint32_t b1 = *(const uint32_t*)&Ks[nt * 8 + g][c + 8];
                        mma_f16_16x8x16(S[nt], qa_f[ks], b0, b1);
                    }
                }

                if (j >= 2 * qt) {
                    #pragma unroll
                    for (int nt = 0; nt < 8; nt++) {
                        int colb = j * 64 + nt * 8 + tig * 2;
                        int r0 = qb + g, r1 = qb + g + 8;
                        if (colb     > r0) S[nt][0] = -1e30f;
                        if (colb + 1 > r0) S[nt][1] = -1e30f;
                        if (colb     > r1) S[nt][2] = -1e30f;
                        if (colb + 1 > r1) S[nt][3] = -1e30f;
                    }
                }

                float mx0 = -1e30f, mx1 = -1e30f;
                #pragma unroll
                for (int nt = 0; nt < 8; nt++) {
                    mx0 = fmaxf(mx0, fmaxf(S[nt][0], S[nt][1]));
                    mx1 = fmaxf(mx1, fmaxf(S[nt][2], S[nt][3]));
                }
                mx0 = fmaxf(mx0, __shfl_xor_sync(0xffffffffu, mx0, 1));
                mx0 = fmaxf(mx0, __shfl_xor_sync(0xffffffffu, mx0, 2));
                mx1 = fmaxf(mx1, __shfl_xor_sync(0xffffffffu, mx1, 1));
                mx1 = fmaxf(mx1, __shfl_xor_sync(0xffffffffu, mx1, 2));

                float mn0 = fmaxf(m0, mx0), mn1 = fmaxf(m1, mx1);
                float al0 = __expf(m0 - mn0), al1 = __expf(m1 - mn1);
                float s0 = 0.0f, s1 = 0.0f;
                #pragma unroll
                for (int nt = 0; nt < 8; nt++) {
                    S[nt][0] = __expf(S[nt][0] - mn0); s0 += S[nt][0];
                    S[nt][1] = __expf(S[nt][1] - mn0); s0 += S[nt][1];
                    S[nt][2] = __expf(S[nt][2] - mn1); s1 += S[nt][2];
                    S[nt][3] = __expf(S[nt][3] - mn1); s1 += S[nt][3];
                }
                s0 += __shfl_xor_sync(0xffffffffu, s0, 1);
                s0 += __shfl_xor_sync(0xffffffffu, s0, 2);
                s1 += __shfl_xor_sync(0xffffffffu, s1, 1);
                s1 += __shfl_xor_sync(0xffffffffu, s1, 2);
                l0 = l0 * al0 + s0;  l1 = l1 * al1 + s1;
                m0 = mn0;            m1 = mn1;

                #pragma unroll
                for (int nt = 0; nt < 8; nt++) {
                    O[nt][0] *= al0; O[nt][1] *= al0;
                    O[nt][2] *= al1; O[nt][3] *= al1;
                }

                #pragma unroll
                for (int nt = 0; nt < 8; nt++) {
                    *(uint32_t*)&Ps[w][g    ][nt * 8 + tig * 2] = pack_h2(S[nt][0], S[nt][1]);
                    *(uint32_t*)&Ps[w][g + 8][nt * 8 + tig * 2] = pack_h2(S[nt][2], S[nt][3]);
                }
                __syncwarp();

                #pragma unroll
                for (int ks = 0; ks < 4; ks++) {
                    int c = ks * 16 + tig * 2;
                    uint32_t a[4];
                    a[0] = *(const uint32_t*)&Ps[w][g    ][c];
                    a[1] = *(const uint32_t*)&Ps[w][g + 8][c];
                    a[2] = *(const uint32_t*)&Ps[w][g    ][c + 8];
                    a[3] = *(const uint32_t*)&Ps[w][g + 8][c + 8];
                    #pragma unroll
                    for (int nt = 0; nt < 8; nt++) {
                        uint32_t b0 = *(const uint32_t*)&Vt[nt * 8 + g][c];
                        uint32_t b1 = *(const uint32_t*)&Vt[nt * 8 + g][c + 8];
                        mma_f16_16x8x16(O[nt], a, b0, b1);
                    }
                }
            }
        }

        float inv0 = 1.0f / l0, inv1 = 1.0f / l1;
        #pragma unroll
        for (int nt = 0; nt < 8; nt++) {
            int col = h * DH + nt * 8 + tig * 2;
            int r0 = qb + g, r1 = qb + g + 8;
            *(float2*)&out[(size_t)(b * SEQ + r0) * DM + col] =
                make_float2(O[nt][0] * inv0, O[nt][1] * inv0);
            *(float2*)&out[(size_t)(b * SEQ + r1) * DM + col] =
                make_float2(O[nt][2] * inv1, O[nt][3] * inv1);
        }
        __syncthreads();   // all warps done before phase 1 reuses smem
    }
}

extern "C" void kernel_launch(void* const* d_in, const int* in_sizes, int n_in,
                              void* d_out, int out_size)
{
    const float* X  = (const float*)d_in[0];
    const float* Wq = (const float*)d_in[1];
    const float* Wk = (const float*)d_in[2];
    const float* Wv = (const float*)d_in[3];
    float* out = (float*)d_out;

    dim3 ggrid(DM / 128, MTOT / 128, 3);
    qkv_gemm_h<<<ggrid, 256>>>(X, Wq, Wk, Wv);

    dim3 agrid(NQT / 2, NH, BATCH);
    attn_tc<<<agrid, 256>>>(out);
}

// round 6
// speedup vs baseline: 7.3473x; 1.3297x over previous
#include <cuda_runtime.h>
#include <cuda_fp16.h>
#include <cuda_bf16.h>
#include <cstdint>

#define BATCH 2
#define SEQ   2048
#define DM    1024
#define NH    16
#define DH    64
#define MTOT  (BATCH*SEQ)   // 4096

// Half-precision staging written by the GEMM epilogue.
__device__ __half g_Qh[MTOT*DM];                 // [b,t,dm], pre-scaled by 1/8
__device__ __half g_Kh[MTOT*DM];                 // [b,t,dm]
__device__ __half g_Vt[MTOT*DM];                 // [b, h*64+d, t]  (transposed)

// fp16 mma m16n8k16, f32 accumulate
__device__ __forceinline__ void mma_f16_16x8x16(float* c, const uint32_t* a, uint32_t b0, uint32_t b1) {
    asm volatile(
        "mma.sync.aligned.m16n8k16.row.col.f32.f16.f16.f32 "
        "{%0,%1,%2,%3}, {%4,%5,%6,%7}, {%8,%9}, {%0,%1,%2,%3};"
        : "+f"(c[0]), "+f"(c[1]), "+f"(c[2]), "+f"(c[3])
        : "r"(a[0]), "r"(a[1]), "r"(a[2]), "r"(a[3]), "r"(b0), "r"(b1));
}

__device__ __forceinline__ uint32_t pack_h2(float lo, float hi) {
    __half2 h = __floats2half2_rn(lo, hi);
    return *(uint32_t*)&h;
}

__device__ __forceinline__ uint32_t smem_u32(const void* p) {
    return (uint32_t)__cvta_generic_to_shared(p);
}

__device__ __forceinline__ void cp16(uint32_t dst, const void* src) {
    asm volatile("cp.async.cg.shared.global [%0], [%1], 16;" :: "r"(dst), "l"(src));
}

// ---------------------------------------------------------------------------
// QKV projection via fp16 mma.sync (fp32 accumulate). 128x128 tile, K chunk 32.
// Epilogue writes half-precision Q (pre-scaled), K, and transposed V.
// ---------------------------------------------------------------------------
#define KT 32
#define KS2 20

__global__ __launch_bounds__(256) void qkv_gemm_h(
    const float* __restrict__ X,
    const float* __restrict__ Wq,
    const float* __restrict__ Wk,
    const float* __restrict__ Wv)
{
    __shared__ uint32_t Xs[128][KS2];
    __shared__ uint32_t Ws[128][KS2];

    const int z = blockIdx.z;
    const float* W = (z == 0) ? Wq : (z == 1) ? Wk : Wv;

    const int m0 = blockIdx.y * 128;
    const int n0 = blockIdx.x * 128;
    const int tid  = threadIdx.x;
    const int wid  = tid >> 5;
    const int lane = tid & 31;
    const int wm = wid >> 2;
    const int wn = wid & 3;
    const int g   = lane >> 2;
    const int tig = lane & 3;

    const int lr  = tid >> 3;
    const int lc4 = (tid & 7) << 2;

    float acc[4][4][4] = {};

    for (int kc = 0; kc < DM / KT; kc++) {
        const int k0 = kc * KT;
        #pragma unroll
        for (int rep = 0; rep < 4; rep++) {
            int row = lr + rep * 32;
            float4 xv = *(const float4*)&X[(size_t)(m0 + row) * DM + k0 + lc4];
            Xs[row][(lc4 >> 1) + 0] = pack_h2(xv.x, xv.y);
            Xs[row][(lc4 >> 1) + 1] = pack_h2(xv.z, xv.w);
            float4 wv = *(const float4*)&W[(size_t)(n0 + row) * DM + k0 + lc4];
            Ws[row][(lc4 >> 1) + 0] = pack_h2(wv.x, wv.y);
            Ws[row][(lc4 >> 1) + 1] = pack_h2(wv.z, wv.w);
        }
        __syncthreads();

        #pragma unroll
        for (int ks = 0; ks < 2; ks++) {
            const int kk = ks * 8;
            uint32_t a[4][4];
            #pragma unroll
            for (int mt = 0; mt < 4; mt++) {
                int mb = wm * 64 + mt * 16;
                a[mt][0] = Xs[mb + g    ][kk + tig    ];
                a[mt][1] = Xs[mb + g + 8][kk + tig    ];
                a[mt][2] = Xs[mb + g    ][kk + tig + 4];
                a[mt][3] = Xs[mb + g + 8][kk + tig + 4];
            }
            uint32_t b[4][2];
            #pragma unroll
            for (int nt = 0; nt < 4; nt++) {
                int nb = wn * 32 + nt * 8 + g;
                b[nt][0] = Ws[nb][kk + tig    ];
                b[nt][1] = Ws[nb][kk + tig + 4];
            }
            #pragma unroll
            for (int mt = 0; mt < 4; mt++)
                #pragma unroll
                for (int nt = 0; nt < 4; nt++)
                    mma_f16_16x8x16(acc[mt][nt], a[mt], b[nt][0], b[nt][1]);
        }
        __syncthreads();
    }

    if (z == 0) {            // Q: half, pre-scaled by 1/sqrt(64)
        const float s = 0.125f;
        #pragma unroll
        for (int mt = 0; mt < 4; mt++) {
            int row = m0 + wm * 64 + mt * 16 + g;
            #pragma unroll
            for (int nt = 0; nt < 4; nt++) {
                int col = n0 + wn * 32 + nt * 8 + tig * 2;
                *(uint32_t*)&g_Qh[(size_t)row * DM + col] =
                    pack_h2(acc[mt][nt][0] * s, acc[mt][nt][1] * s);
                *(uint32_t*)&g_Qh[(size_t)(row + 8) * DM + col] =
                    pack_h2(acc[mt][nt][2] * s, acc[mt][nt][3] * s);
            }
        }
    } else if (z == 1) {     // K: half
        #pragma unroll
        for (int mt = 0; mt < 4; mt++) {
            int row = m0 + wm * 64 + mt * 16 + g;
            #pragma unroll
            for (int nt = 0; nt < 4; nt++) {
                int col = n0 + wn * 32 + nt * 8 + tig * 2;
                *(uint32_t*)&g_Kh[(size_t)row * DM + col] =
                    pack_h2(acc[mt][nt][0], acc[mt][nt][1]);
                *(uint32_t*)&g_Kh[(size_t)(row + 8) * DM + col] =
                    pack_h2(acc[mt][nt][2], acc[mt][nt][3]);
            }
        }
    } else {                 // V: half, transposed [b, dm, t]
        #pragma unroll
        for (int mt = 0; mt < 4; mt++) {
            int row = m0 + wm * 64 + mt * 16 + g;
            int bz = row >> 11;           // SEQ = 2048
            int t  = row & (SEQ - 1);
            #pragma unroll
            for (int nt = 0; nt < 4; nt++) {
                int col = n0 + wn * 32 + nt * 8 + tig * 2;
                size_t c0 = ((size_t)bz * DM + col) * SEQ;
                size_t c1 = ((size_t)bz * DM + col + 1) * SEQ;
                g_Vt[c0 + t]     = __float2half(acc[mt][nt][0]);
                g_Vt[c1 + t]     = __float2half(acc[mt][nt][1]);
                g_Vt[c0 + t + 8] = __float2half(acc[mt][nt][2]);
                g_Vt[c1 + t + 8] = __float2half(acc[mt][nt][3]);
            }
        }
    }
}

// ---------------------------------------------------------------------------
// Tensor-core flash attention: fp16 mma, register-direct P, cp.async
// double-buffered K/V tiles, work-paired CTAs (qa, 15-qa).
// Grid (8, NH, BATCH) = 256 CTAs, 256 threads.
// ---------------------------------------------------------------------------
#define HSTR 72
#define NQT  (SEQ / 128)   // 16

__global__ __launch_bounds__(256, 2) void attn_tc(float* __restrict__ out)
{
    const int qa = blockIdx.x;
    const int h  = blockIdx.y;
    const int b  = blockIdx.z;

    __shared__ __half Ks[2][64][HSTR];
    __shared__ __half Vt[2][64][HSTR];

    const int tid  = threadIdx.x;
    const int w    = tid >> 5;
    const int lane = tid & 31;
    const int g    = lane >> 2;
    const int tig  = lane & 3;

    const __half* Qg = g_Qh + (size_t)b * SEQ * DM + h * DH;
    const __half* Kg = g_Kh + (size_t)b * SEQ * DM + h * DH;
    const __half* Vg = g_Vt + ((size_t)b * DM + h * DH) * SEQ;

    const int lr  = tid >> 2;        // 0..63 row (K: token; V: dim)
    const int lcb = (tid & 3) * 32;  // byte offset within 128B row

    #pragma unroll 1
    for (int phase = 0; phase < 2; phase++) {
        const int qt = phase ? (NQT - 1 - qa) : qa;
        const int qb = qt * 128 + w * 16;

        // Q fragments (already half + pre-scaled in gmem)
        uint32_t qf[4][4];
        #pragma unroll
        for (int ks = 0; ks < 4; ks++) {
            int c = ks * 16 + tig * 2;
            qf[ks][0] = *(const uint32_t*)&Qg[(size_t)(qb + g    ) * DM + c];
            qf[ks][1] = *(const uint32_t*)&Qg[(size_t)(qb + g + 8) * DM + c];
            qf[ks][2] = *(const uint32_t*)&Qg[(size_t)(qb + g    ) * DM + c + 8];
            qf[ks][3] = *(const uint32_t*)&Qg[(size_t)(qb + g + 8) * DM + c + 8];
        }

        float m0 = -1e30f, m1 = -1e30f, l0 = 0.0f, l1 = 0.0f;
        float O[8][4] = {};

        const int jmax = 2 * qt + 1;

        // prologue: tile 0 -> buffer 0
        {
            const char* ksrc = (const char*)&Kg[(size_t)(0 * 64 + lr) * DM] + lcb;
            uint32_t kdst = smem_u32(&Ks[0][lr][0]) + lcb;
            cp16(kdst, ksrc); cp16(kdst + 16, ksrc + 16);
            const char* vsrc = (const char*)&Vg[(size_t)lr * SEQ + 0] + lcb;
            uint32_t vdst = smem_u32(&Vt[0][lr][0]) + lcb;
            cp16(vdst, vsrc); cp16(vdst + 16, vsrc + 16);
            asm volatile("cp.async.commit_group;");
        }

        for (int j = 0; j <= jmax; j++) {
            const int bf = j & 1;
            if (j < jmax) {
                const int jn = j + 1, bn = jn & 1;
                const char* ksrc = (const char*)&Kg[(size_t)(jn * 64 + lr) * DM] + lcb;
                uint32_t kdst = smem_u32(&Ks[bn][lr][0]) + lcb;
                cp16(kdst, ksrc); cp16(kdst + 16, ksrc + 16);
                const char* vsrc = (const char*)&Vg[(size_t)lr * SEQ + jn * 64] + lcb;
                uint32_t vdst = smem_u32(&Vt[bn][lr][0]) + lcb;
                cp16(vdst, vsrc); cp16(vdst + 16, vsrc + 16);
                asm volatile("cp.async.commit_group;");
                asm volatile("cp.async.wait_group 1;");
            } else {
                asm volatile("cp.async.wait_group 0;");
            }
            __syncthreads();

            if (j * 64 <= qb + 15) {
                // S = Q K^T (16 x 64 per warp)
                float S[8][4] = {};
                #pragma unroll
                for (int ks = 0; ks < 4; ks++) {
                    int c = ks * 16 + tig * 2;
                    #pragma unroll
                    for (int nt = 0; nt < 8; nt++) {
                        uint32_t b0 = *(const uint32_t*)&Ks[bf][nt * 8 + g][c];
                        uint32_t b1 = *(const uint32_t*)&Ks[bf][nt * 8 + g][c + 8];
                        mma_f16_16x8x16(S[nt], qf[ks], b0, b1);
                    }
                }

                if (j >= 2 * qt) {       // diagonal tiles: causal mask
                    #pragma unroll
                    for (int nt = 0; nt < 8; nt++) {
                        int colb = j * 64 + nt * 8 + tig * 2;
                        int r0 = qb + g, r1 = qb + g + 8;
                        if (colb     > r0) S[nt][0] = -1e30f;
                        if (colb + 1 > r0) S[nt][1] = -1e30f;
                        if (colb     > r1) S[nt][2] = -1e30f;
                        if (colb + 1 > r1) S[nt][3] = -1e30f;
                    }
                }

                // online softmax (rows g / g+8), quad-lane reductions
                float mx0 = -1e30f, mx1 = -1e30f;
                #pragma unroll
                for (int nt = 0; nt < 8; nt++) {
                    mx0 = fmaxf(mx0, fmaxf(S[nt][0], S[nt][1]));
                    mx1 = fmaxf(mx1, fmaxf(S[nt][2], S[nt][3]));
                }
                mx0 = fmaxf(mx0, __shfl_xor_sync(0xffffffffu, mx0, 1));
                mx0 = fmaxf(mx0, __shfl_xor_sync(0xffffffffu, mx0, 2));
                mx1 = fmaxf(mx1, __shfl_xor_sync(0xffffffffu, mx1, 1));
                mx1 = fmaxf(mx1, __shfl_xor_sync(0xffffffffu, mx1, 2));

                float mn0 = fmaxf(m0, mx0), mn1 = fmaxf(m1, mx1);
                float al0 = __expf(m0 - mn0), al1 = __expf(m1 - mn1);
                float s0 = 0.0f, s1 = 0.0f;
                #pragma unroll
                for (int nt = 0; nt < 8; nt++) {
                    S[nt][0] = __expf(S[nt][0] - mn0); s0 += S[nt][0];
                    S[nt][1] = __expf(S[nt][1] - mn0); s0 += S[nt][1];
                    S[nt][2] = __expf(S[nt][2] - mn1); s1 += S[nt][2];
                    S[nt][3] = __expf(S[nt][3] - mn1); s1 += S[nt][3];
                }
                s0 += __shfl_xor_sync(0xffffffffu, s0, 1);
                s0 += __shfl_xor_sync(0xffffffffu, s0, 2);
                s1 += __shfl_xor_sync(0xffffffffu, s1, 1);
                s1 += __shfl_xor_sync(0xffffffffu, s1, 2);
                l0 = l0 * al0 + s0;  l1 = l1 * al1 + s1;
                m0 = mn0;            m1 = mn1;

                #pragma unroll
                for (int nt = 0; nt < 8; nt++) {
                    O[nt][0] *= al0; O[nt][1] *= al0;
                    O[nt][2] *= al1; O[nt][3] *= al1;
                }

                // O += P V, P taken straight from S registers (FA2 layout trick)
                #pragma unroll
                for (int ks = 0; ks < 4; ks++) {
                    uint32_t a[4];
                    a[0] = pack_h2(S[2*ks    ][0], S[2*ks    ][1]);
                    a[1] = pack_h2(S[2*ks    ][2], S[2*ks    ][3]);
                    a[2] = pack_h2(S[2*ks + 1][0], S[2*ks + 1][1]);
                    a[3] = pack_h2(S[2*ks + 1][2], S[2*ks + 1][3]);
                    int c = ks * 16 + tig * 2;
                    #pragma unroll
                    for (int nt = 0; nt < 8; nt++) {
                        uint32_t b0 = *(const uint32_t*)&Vt[bf][nt * 8 + g][c];
                        uint32_t b1 = *(const uint32_t*)&Vt[bf][nt * 8 + g][c + 8];
                        mma_f16_16x8x16(O[nt], a, b0, b1);
                    }
                }
            }
            __syncthreads();   // all warps done with buffer bf before it is refilled
        }

        float inv0 = 1.0f / l0, inv1 = 1.0f / l1;
        #pragma unroll
        for (int nt = 0; nt < 8; nt++) {
            int col = h * DH + nt * 8 + tig * 2;
            int r0 = qb + g, r1 = qb + g + 8;
            *(float2*)&out[(size_t)(b * SEQ + r0) * DM + col] =
                make_float2(O[nt][0] * inv0, O[nt][1] * inv0);
            *(float2*)&out[(size_t)(b * SEQ + r1) * DM + col] =
                make_float2(O[nt][2] * inv1, O[nt][3] * inv1);
        }
    }
}

extern "C" void kernel_launch(void* const* d_in, const int* in_sizes, int n_in,
                              void* d_out, int out_size)
{
    const float* X  = (const float*)d_in[0];
    const float* Wq = (const float*)d_in[1];
    const float* Wk = (const float*)d_in[2];
    const float* Wv = (const float*)d_in[3];
    float* out = (float*)d_out;

    dim3 ggrid(DM / 128, MTOT / 128, 3);
    qkv_gemm_h<<<ggrid, 256>>>(X, Wq, Wk, Wv);

    dim3 agrid(NQT / 2, NH, BATCH);
    attn_tc<<<agrid, 256>>>(out);
}